// round 1
// baseline (speedup 1.0000x reference)
#include <cuda_runtime.h>
#include <math.h>

#define BB 4
#define SS 1024
#define DD 1024
#define HH 16
#define DK 64
#define DFF 4096

// ---------------- scratch (device globals; no allocations allowed) ----------
__device__ float g_wq[DD * DD];
__device__ float g_wk[DD * DD];
__device__ float g_wv[DD * DD];
__device__ float g_q[BB * SS * DD];       // q [B,S,H,DK]; reused as mha_out
__device__ float g_k[BB * SS * DD];       // k [B,S,H,DK]; reused as sub1
__device__ float g_v[BB * SS * DD];       // v [B,S,H,DK]; reused as ffn2 out
__device__ float g_scores[(long long)BB * HH * SS * SS]; // 256 MB
__device__ float g_concat[BB * SS * DD];
__device__ float g_ffn1[(long long)BB * SS * DFF];

// ---------------- repack per-head weights [H,D,DK] -> [D, H*DK] -------------
__global__ void repack_kernel(const float* __restrict__ wq,
                              const float* __restrict__ wk,
                              const float* __restrict__ wv) {
    int idx = blockIdx.x * 256 + threadIdx.x;     // over D*D
    int d = idx >> 10;
    int c = idx & 1023;                            // c = h*DK + k
    int src = ((c >> 6) << 16) | (d << 6) | (c & 63); // h*D*DK + d*DK + k
    g_wq[idx] = wq[src];
    g_wk[idx] = wk[src];
    g_wv[idx] = wv[src];
}

// ---------------- generic strided/batched tiled GEMM ------------------------
// C = alpha * A @ B (+bias) (+relu). Batch index z = bz*Hn + hz with separate
// per-h / per-b offsets so [B,S,H,DK] views work without linear batch stride.
template <int TRANSB, int RELU>
__global__ __launch_bounds__(256) void gemm_kernel(
    const float* __restrict__ A, const float* __restrict__ Bm,
    const float* __restrict__ bias, float* __restrict__ C,
    int M, int N, int K, int lda, int ldb, int ldc,
    int Hn, long long sAh, long long sAb, long long sBh, long long sBb,
    long long sCh, long long sCb, float alpha) {
    int z = blockIdx.z;
    int hz = z % Hn, bz = z / Hn;
    A  += (long long)hz * sAh + (long long)bz * sAb;
    Bm += (long long)hz * sBh + (long long)bz * sBb;
    C  += (long long)hz * sCh + (long long)bz * sCb;

    __shared__ float As[16][64 + 4];
    __shared__ float Bs[16][64 + 4];

    int tid = threadIdx.x;
    int tx = tid & 15, ty = tid >> 4;
    int row0 = blockIdx.y * 64;
    int col0 = blockIdx.x * 64;

    float acc[4][4] = {};

    for (int k0 = 0; k0 < K; k0 += 16) {
        // A tile: 64 (m) x 16 (k), coalesced over k
        #pragma unroll
        for (int i = 0; i < 4; i++) {
            int m = (tid >> 4) + 16 * i;
            int kk = tid & 15;
            As[kk][m] = A[(long long)(row0 + m) * lda + (k0 + kk)];
        }
        if (TRANSB) {
            #pragma unroll
            for (int i = 0; i < 4; i++) {
                int n = (tid >> 4) + 16 * i;
                int kk = tid & 15;
                Bs[kk][n] = Bm[(long long)(col0 + n) * ldb + (k0 + kk)];
            }
        } else {
            #pragma unroll
            for (int i = 0; i < 4; i++) {
                int kk = (tid >> 6) + 4 * i;
                int n = tid & 63;
                Bs[kk][n] = Bm[(long long)(k0 + kk) * ldb + (col0 + n)];
            }
        }
        __syncthreads();
        #pragma unroll
        for (int kk = 0; kk < 16; kk++) {
            float4 av = *(const float4*)&As[kk][ty * 4];
            float4 bv = *(const float4*)&Bs[kk][tx * 4];
            float a[4] = {av.x, av.y, av.z, av.w};
            float b[4] = {bv.x, bv.y, bv.z, bv.w};
            #pragma unroll
            for (int i = 0; i < 4; i++)
                #pragma unroll
                for (int j = 0; j < 4; j++)
                    acc[i][j] += a[i] * b[j];
        }
        __syncthreads();
    }

    #pragma unroll
    for (int i = 0; i < 4; i++) {
        int r = row0 + ty * 4 + i;
        #pragma unroll
        for (int j = 0; j < 4; j++) {
            int c = col0 + tx * 4 + j;
            float v = acc[i][j] * alpha;
            if (bias) v += bias[c];
            if (RELU) v = fmaxf(v, 0.0f);
            C[(long long)r * ldc + c] = v;
        }
    }
}

// ---------------- softmax over rows of g_scores; emits last head -----------
__global__ __launch_bounds__(256) void softmax_kernel(
    float* __restrict__ scores, const float* __restrict__ mask,
    float* __restrict__ out_attn) {
    long long r = blockIdx.x;               // 0 .. B*H*S-1
    int s = (int)(r & (SS - 1));
    int h = (int)((r >> 10) & (HH - 1));
    int b = (int)(r >> 14);
    float* row = scores + r * SS;
    const float* mrow = mask + (long long)b * SS;
    int tid = threadIdx.x;

    float vals[4];
    float mx = -1e30f;
    #pragma unroll
    for (int i = 0; i < 4; i++) {
        int t = tid + 256 * i;
        float v = row[t] + mrow[t] * (-1e9f);
        vals[i] = v;
        mx = fmaxf(mx, v);
    }
    __shared__ float red[256];
    red[tid] = mx;
    __syncthreads();
    for (int off = 128; off > 0; off >>= 1) {
        if (tid < off) red[tid] = fmaxf(red[tid], red[tid + off]);
        __syncthreads();
    }
    mx = red[0];
    __syncthreads();

    float sum = 0.0f;
    #pragma unroll
    for (int i = 0; i < 4; i++) {
        vals[i] = __expf(vals[i] - mx);
        sum += vals[i];
    }
    red[tid] = sum;
    __syncthreads();
    for (int off = 128; off > 0; off >>= 1) {
        if (tid < off) red[tid] += red[tid + off];
        __syncthreads();
    }
    float inv = 1.0f / red[0];

    #pragma unroll
    for (int i = 0; i < 4; i++) {
        int t = tid + 256 * i;
        float p = vals[i] * inv;
        row[t] = p;
        if (h == HH - 1)
            out_attn[((long long)(b * SS + s)) * SS + t] = p;
    }
}

// ---------------- residual add + layernorm ---------------------------------
__global__ __launch_bounds__(256) void add_ln_kernel(
    const float* __restrict__ xa, const float* __restrict__ xb,
    const float* __restrict__ g, const float* __restrict__ bt,
    float* __restrict__ out) {
    long long r = blockIdx.x;               // 0 .. B*S-1
    const float* pa = xa + r * DD;
    const float* pb = xb + r * DD;
    float* po = out + r * DD;
    int tid = threadIdx.x;

    float v[4];
    float sum = 0.0f, sq = 0.0f;
    #pragma unroll
    for (int i = 0; i < 4; i++) {
        int c = tid + 256 * i;
        float x = pa[c] + pb[c];
        v[i] = x;
        sum += x;
        sq += x * x;
    }
    __shared__ float r1[256], r2[256];
    r1[tid] = sum;
    r2[tid] = sq;
    __syncthreads();
    for (int off = 128; off > 0; off >>= 1) {
        if (tid < off) { r1[tid] += r1[tid + off]; r2[tid] += r2[tid + off]; }
        __syncthreads();
    }
    float mu = r1[0] * (1.0f / DD);
    float var = r2[0] * (1.0f / DD) - mu * mu;
    float rstd = rsqrtf(var + 1e-6f);

    #pragma unroll
    for (int i = 0; i < 4; i++) {
        int c = tid + 256 * i;
        po[c] = (v[i] - mu) * rstd * g[c] + bt[c];
    }
}

// ---------------- launch ----------------------------------------------------
extern "C" void kernel_launch(void* const* d_in, const int* in_sizes, int n_in,
                              void* d_out, int out_size) {
    const float* x_v   = (const float*)d_in[0];
    const float* x_k   = (const float*)d_in[1];
    const float* x_q   = (const float*)d_in[2];
    const float* mask  = (const float*)d_in[3];
    const float* wq    = (const float*)d_in[4];
    const float* bq    = (const float*)d_in[5];
    const float* wk    = (const float*)d_in[6];
    const float* bk    = (const float*)d_in[7];
    const float* wv    = (const float*)d_in[8];
    const float* bv    = (const float*)d_in[9];
    const float* w0    = (const float*)d_in[10];
    const float* b0    = (const float*)d_in[11];
    const float* ln1_g = (const float*)d_in[12];
    const float* ln1_b = (const float*)d_in[13];
    const float* ff1_w = (const float*)d_in[14];
    const float* ff1_b = (const float*)d_in[15];
    const float* ff2_w = (const float*)d_in[16];
    const float* ff2_b = (const float*)d_in[17];
    const float* ln2_g = (const float*)d_in[18];
    const float* ln2_b = (const float*)d_in[19];

    float* out = (float*)d_out;
    float* out_attn = out + (long long)BB * SS * DD;

    float *pwq, *pwk, *pwv, *pq, *pk, *pv, *pscores, *pconcat, *pffn1;
    cudaGetSymbolAddress((void**)&pwq, g_wq);
    cudaGetSymbolAddress((void**)&pwk, g_wk);
    cudaGetSymbolAddress((void**)&pwv, g_wv);
    cudaGetSymbolAddress((void**)&pq, g_q);
    cudaGetSymbolAddress((void**)&pk, g_k);
    cudaGetSymbolAddress((void**)&pv, g_v);
    cudaGetSymbolAddress((void**)&pscores, g_scores);
    cudaGetSymbolAddress((void**)&pconcat, g_concat);
    cudaGetSymbolAddress((void**)&pffn1, g_ffn1);

    const long long SD  = (long long)SS * DD;        // per-batch stride of [B,S,D]
    const long long SSq = (long long)SS * SS;        // per-head stride of scores
    dim3 blk(256);
    const int MT = BB * SS;                          // 4096 token rows

    // repack per-head projection weights into [D, D]
    repack_kernel<<<(DD * DD) / 256, 256>>>(wq, wk, wv);

    // q/k/v projections: [4096,1024] @ [1024,1024] + bias
    gemm_kernel<0, 0><<<dim3(16, 64, 1), blk>>>(x_q, pwq, bq, pq,
        MT, DD, DD, DD, DD, DD, 1, 0, 0, 0, 0, 0, 0, 1.0f);
    gemm_kernel<0, 0><<<dim3(16, 64, 1), blk>>>(x_k, pwk, bk, pk,
        MT, DD, DD, DD, DD, DD, 1, 0, 0, 0, 0, 0, 0, 1.0f);
    gemm_kernel<0, 0><<<dim3(16, 64, 1), blk>>>(x_v, pwv, bv, pv,
        MT, DD, DD, DD, DD, DD, 1, 0, 0, 0, 0, 0, 0, 1.0f);

    // scores = Q K^T / sqrt(DK), batched over B*H
    gemm_kernel<1, 0><<<dim3(16, 16, BB * HH), blk>>>(pq, pk, nullptr, pscores,
        SS, SS, DK, DD, DD, SS,
        HH, DK, SD, DK, SD, SSq, (long long)HH * SSq, 0.125f);

    // softmax (+mask) in place; last head -> d_out second half
    softmax_kernel<<<BB * HH * SS, blk>>>(pscores, mask, out_attn);

    // attn @ V -> concat [B,S,H*DK]
    gemm_kernel<0, 0><<<dim3(1, 16, BB * HH), blk>>>(pscores, pv, nullptr, pconcat,
        SS, DK, SS, SS, DD, DD,
        HH, SSq, (long long)HH * SSq, DK, SD, DK, SD, 1.0f);

    // mha_out = concat @ w0 + b0   (reuse g_q)
    gemm_kernel<0, 0><<<dim3(16, 64, 1), blk>>>(pconcat, w0, b0, pq,
        MT, DD, DD, DD, DD, DD, 1, 0, 0, 0, 0, 0, 0, 1.0f);

    // sub1 = LN1(x_q + mha_out)    (reuse g_k)
    add_ln_kernel<<<MT, blk>>>(x_q, pq, ln1_g, ln1_b, pk);

    // ffn1 = relu(sub1 @ ff1_w + ff1_b)
    gemm_kernel<0, 1><<<dim3(64, 64, 1), blk>>>(pk, ff1_w, ff1_b, pffn1,
        MT, DFF, DD, DD, DFF, DFF, 1, 0, 0, 0, 0, 0, 0, 1.0f);

    // ffn2 = ffn1 @ ff2_w + ff2_b  (reuse g_v)
    gemm_kernel<0, 0><<<dim3(16, 64, 1), blk>>>(pffn1, ff2_w, ff2_b, pv,
        MT, DD, DFF, DFF, DD, DD, 1, 0, 0, 0, 0, 0, 0, 1.0f);

    // out = LN2(sub1 + ffn2) -> d_out first half
    add_ln_kernel<<<MT, blk>>>(pk, pv, ln2_g, ln2_b, out);
}

// round 2
// speedup vs baseline: 2.5992x; 2.5992x over previous
#include <cuda_runtime.h>
#include <math.h>
#include <stdint.h>

#define BB 4
#define SS 1024
#define DD 1024
#define HH 16
#define DK 64
#define DFF 4096

// ---------------- scratch (device globals; no allocations allowed) ----------
__device__ float g_wq[DD * DD];
__device__ float g_wk[DD * DD];
__device__ float g_wv[DD * DD];
__device__ float g_q[BB * SS * DD];       // q [B,S,H,DK]; reused as mha_out
__device__ float g_k[BB * SS * DD];       // k [B,S,H,DK]; reused as sub1
__device__ float g_v[BB * SS * DD];       // v [B,S,H,DK]; reused as ffn2 out
__device__ float g_scores[(long long)BB * HH * SS * SS]; // 256 MB
__device__ float g_concat[BB * SS * DD];
__device__ float g_ffn1[(long long)BB * SS * DFF];

// ---------------- tf32 helpers ----------------------------------------------
__device__ __forceinline__ uint32_t f2tf32(float x) {
    uint32_t u;
    asm("cvt.rna.tf32.f32 %0, %1;" : "=r"(u) : "f"(x));
    return u;
}

__device__ __forceinline__ void mma8(float* d, const uint32_t* a, const uint32_t* b) {
    asm volatile(
        "mma.sync.aligned.m16n8k8.row.col.f32.tf32.tf32.f32 "
        "{%0,%1,%2,%3}, {%4,%5,%6,%7}, {%8,%9}, {%0,%1,%2,%3};"
        : "+f"(d[0]), "+f"(d[1]), "+f"(d[2]), "+f"(d[3])
        : "r"(a[0]), "r"(a[1]), "r"(a[2]), "r"(a[3]), "r"(b[0]), "r"(b[1]));
}

// ---------------- repack per-head weights [H,D,DK] -> [D, H*DK] -------------
__global__ void repack_kernel(const float* __restrict__ wq,
                              const float* __restrict__ wk,
                              const float* __restrict__ wv) {
    int idx = blockIdx.x * 256 + threadIdx.x;     // over D*D
    int d = idx >> 10;
    int c = idx & 1023;                            // c = h*DK + k
    int src = ((c >> 6) << 16) | (d << 6) | (c & 63); // h*D*DK + d*DK + k
    g_wq[idx] = wq[src];
    g_wk[idx] = wk[src];
    g_wv[idx] = wv[src];
}

// ---------------- TF32 tensor-core tiled GEMM -------------------------------
// C = alpha * A @ B (+bias) (+relu). Batch z = bz*Hn + hz, separate h/b strides.
// Block tile BM x BN, BK=32. 8 warps (2 x 4), warp tile (BM/2) x (BN/4).
// All problem dims must be multiples of the tile dims (true for this problem).
template <int BM, int BN, int TRANSB, int RELU>
__global__ __launch_bounds__(256) void gemm_tc(
    const float* __restrict__ A, const float* __restrict__ Bm,
    const float* __restrict__ bias, float* __restrict__ C,
    int K, int lda, int ldb, int ldc,
    int Hn, long long sAh, long long sAb, long long sBh, long long sBb,
    long long sCh, long long sCb, float alpha) {
    constexpr int BK = 32;
    constexpr int WM = BM / 2, WN = BN / 4;
    constexpr int MT = WM / 16, NT = WN / 8;
    constexpr int AV = BM * BK / 1024;   // float4 per thread for A tile
    constexpr int BV = BK * BN / 1024;   // float4 per thread for B tile

    __shared__ uint32_t As[BM][BK + 4];  // [m][k], stride 36: frag loads conflict-free
    __shared__ uint32_t Bs[BK][BN + 8];  // [k][n], stride%32==8: frag loads conflict-free

    int z = blockIdx.z;
    int hz = z % Hn, bz = z / Hn;
    A  += (long long)hz * sAh + (long long)bz * sAb;
    Bm += (long long)hz * sBh + (long long)bz * sBb;
    C  += (long long)hz * sCh + (long long)bz * sCb;

    const int tid = threadIdx.x;
    const int lane = tid & 31, warp = tid >> 5;
    const int wrow = warp >> 2, wcol = warp & 3;
    const int row0 = blockIdx.y * BM, col0 = blockIdx.x * BN;

    float4 pa[AV], pb[BV];
    const int nk = K / BK;

    auto loadA = [&](int kt) {
        #pragma unroll
        for (int i = 0; i < AV; i++) {
            int idx = tid + 256 * i;
            int m = idx >> 3, c4 = (idx & 7) * 4;
            pa[i] = *(const float4*)(A + (long long)(row0 + m) * lda + kt * BK + c4);
        }
    };
    auto loadB = [&](int kt) {
        if (TRANSB) {
            #pragma unroll
            for (int i = 0; i < BV; i++) {
                int idx = tid + 256 * i;
                int n = idx >> 3, c4 = (idx & 7) * 4;
                pb[i] = *(const float4*)(Bm + (long long)(col0 + n) * ldb + kt * BK + c4);
            }
        } else {
            #pragma unroll
            for (int i = 0; i < BV; i++) {
                int idx = tid + 256 * i;
                int kk = idx / (BN / 4), c4 = (idx % (BN / 4)) * 4;
                pb[i] = *(const float4*)(Bm + (long long)(kt * BK + kk) * ldb + col0 + c4);
            }
        }
    };
    auto stsA = [&]() {
        #pragma unroll
        for (int i = 0; i < AV; i++) {
            int idx = tid + 256 * i;
            int m = idx >> 3, c4 = (idx & 7) * 4;
            const float* f = (const float*)&pa[i];
            #pragma unroll
            for (int j = 0; j < 4; j++) As[m][c4 + j] = f2tf32(f[j]);
        }
    };
    auto stsB = [&]() {
        if (TRANSB) {
            #pragma unroll
            for (int i = 0; i < BV; i++) {
                int idx = tid + 256 * i;
                int n = idx >> 3, c4 = (idx & 7) * 4;
                const float* f = (const float*)&pb[i];
                #pragma unroll
                for (int j = 0; j < 4; j++) Bs[c4 + j][n] = f2tf32(f[j]);
            }
        } else {
            #pragma unroll
            for (int i = 0; i < BV; i++) {
                int idx = tid + 256 * i;
                int kk = idx / (BN / 4), c4 = (idx % (BN / 4)) * 4;
                const float* f = (const float*)&pb[i];
                uint4 u;
                u.x = f2tf32(f[0]); u.y = f2tf32(f[1]);
                u.z = f2tf32(f[2]); u.w = f2tf32(f[3]);
                *(uint4*)&Bs[kk][c4] = u;
            }
        }
    };

    float acc[MT][NT][4] = {};

    loadA(0); loadB(0);
    stsA(); stsB();
    __syncthreads();

    for (int kt = 0; kt < nk; kt++) {
        if (kt + 1 < nk) { loadA(kt + 1); loadB(kt + 1); }

        const int r = lane >> 2, c = lane & 3;
        #pragma unroll
        for (int ks = 0; ks < 4; ks++) {
            const int k0 = ks * 8;
            uint32_t af[MT][4], bf[NT][2];
            #pragma unroll
            for (int mt = 0; mt < MT; mt++) {
                int m = wrow * WM + mt * 16 + r;
                af[mt][0] = As[m][k0 + c];
                af[mt][1] = As[m + 8][k0 + c];
                af[mt][2] = As[m][k0 + c + 4];
                af[mt][3] = As[m + 8][k0 + c + 4];
            }
            #pragma unroll
            for (int nt = 0; nt < NT; nt++) {
                int n = wcol * WN + nt * 8 + r;
                bf[nt][0] = Bs[k0 + c][n];
                bf[nt][1] = Bs[k0 + c + 4][n];
            }
            #pragma unroll
            for (int mt = 0; mt < MT; mt++)
                #pragma unroll
                for (int nt = 0; nt < NT; nt++)
                    mma8(acc[mt][nt], af[mt], bf[nt]);
        }
        __syncthreads();
        if (kt + 1 < nk) { stsA(); stsB(); __syncthreads(); }
    }

    // epilogue
    const int r = lane >> 2, c2 = (lane & 3) * 2;
    #pragma unroll
    for (int mt = 0; mt < MT; mt++) {
        int mrow = row0 + wrow * WM + mt * 16 + r;
        #pragma unroll
        for (int nt = 0; nt < NT; nt++) {
            int ncol = col0 + wcol * WN + nt * 8 + c2;
            float b0 = 0.0f, b1 = 0.0f;
            if (bias) { b0 = bias[ncol]; b1 = bias[ncol + 1]; }
            float v0 = acc[mt][nt][0] * alpha + b0;
            float v1 = acc[mt][nt][1] * alpha + b1;
            float v2 = acc[mt][nt][2] * alpha + b0;
            float v3 = acc[mt][nt][3] * alpha + b1;
            if (RELU) {
                v0 = fmaxf(v0, 0.0f); v1 = fmaxf(v1, 0.0f);
                v2 = fmaxf(v2, 0.0f); v3 = fmaxf(v3, 0.0f);
            }
            float2 w0 = make_float2(v0, v1);
            float2 w1 = make_float2(v2, v3);
            *(float2*)(C + (long long)mrow * ldc + ncol) = w0;
            *(float2*)(C + (long long)(mrow + 8) * ldc + ncol) = w1;
        }
    }
}

// ---------------- softmax over rows of g_scores; emits last head -----------
__global__ __launch_bounds__(256) void softmax_kernel(
    float* __restrict__ scores, const float* __restrict__ mask,
    float* __restrict__ out_attn) {
    long long r = blockIdx.x;               // 0 .. B*H*S-1
    int s = (int)(r & (SS - 1));
    int h = (int)((r >> 10) & (HH - 1));
    int b = (int)(r >> 14);
    float* row = scores + r * SS;
    const float* mrow = mask + (long long)b * SS;
    int tid = threadIdx.x;

    float vals[4];
    float mx = -1e30f;
    #pragma unroll
    for (int i = 0; i < 4; i++) {
        int t = tid + 256 * i;
        float v = row[t] + mrow[t] * (-1e9f);
        vals[i] = v;
        mx = fmaxf(mx, v);
    }
    __shared__ float red[256];
    red[tid] = mx;
    __syncthreads();
    for (int off = 128; off > 0; off >>= 1) {
        if (tid < off) red[tid] = fmaxf(red[tid], red[tid + off]);
        __syncthreads();
    }
    mx = red[0];
    __syncthreads();

    float sum = 0.0f;
    #pragma unroll
    for (int i = 0; i < 4; i++) {
        vals[i] = __expf(vals[i] - mx);
        sum += vals[i];
    }
    red[tid] = sum;
    __syncthreads();
    for (int off = 128; off > 0; off >>= 1) {
        if (tid < off) red[tid] += red[tid + off];
        __syncthreads();
    }
    float inv = 1.0f / red[0];

    #pragma unroll
    for (int i = 0; i < 4; i++) {
        int t = tid + 256 * i;
        float p = vals[i] * inv;
        row[t] = p;
        if (h == HH - 1)
            out_attn[((long long)(b * SS + s)) * SS + t] = p;
    }
}

// ---------------- residual add + layernorm ---------------------------------
__global__ __launch_bounds__(256) void add_ln_kernel(
    const float* __restrict__ xa, const float* __restrict__ xb,
    const float* __restrict__ g, const float* __restrict__ bt,
    float* __restrict__ out) {
    long long r = blockIdx.x;               // 0 .. B*S-1
    const float* pa = xa + r * DD;
    const float* pb = xb + r * DD;
    float* po = out + r * DD;
    int tid = threadIdx.x;

    float v[4];
    float sum = 0.0f, sq = 0.0f;
    #pragma unroll
    for (int i = 0; i < 4; i++) {
        int c = tid + 256 * i;
        float x = pa[c] + pb[c];
        v[i] = x;
        sum += x;
        sq += x * x;
    }
    __shared__ float r1[256], r2[256];
    r1[tid] = sum;
    r2[tid] = sq;
    __syncthreads();
    for (int off = 128; off > 0; off >>= 1) {
        if (tid < off) { r1[tid] += r1[tid + off]; r2[tid] += r2[tid + off]; }
        __syncthreads();
    }
    float mu = r1[0] * (1.0f / DD);
    float var = r2[0] * (1.0f / DD) - mu * mu;
    float rstd = rsqrtf(var + 1e-6f);

    #pragma unroll
    for (int i = 0; i < 4; i++) {
        int c = tid + 256 * i;
        po[c] = (v[i] - mu) * rstd * g[c] + bt[c];
    }
}

// ---------------- launch ----------------------------------------------------
extern "C" void kernel_launch(void* const* d_in, const int* in_sizes, int n_in,
                              void* d_out, int out_size) {
    const float* x_v   = (const float*)d_in[0];
    const float* x_k   = (const float*)d_in[1];
    const float* x_q   = (const float*)d_in[2];
    const float* mask  = (const float*)d_in[3];
    const float* wq    = (const float*)d_in[4];
    const float* bq    = (const float*)d_in[5];
    const float* wk    = (const float*)d_in[6];
    const float* bk    = (const float*)d_in[7];
    const float* wv    = (const float*)d_in[8];
    const float* bv    = (const float*)d_in[9];
    const float* w0    = (const float*)d_in[10];
    const float* b0    = (const float*)d_in[11];
    const float* ln1_g = (const float*)d_in[12];
    const float* ln1_b = (const float*)d_in[13];
    const float* ff1_w = (const float*)d_in[14];
    const float* ff1_b = (const float*)d_in[15];
    const float* ff2_w = (const float*)d_in[16];
    const float* ff2_b = (const float*)d_in[17];
    const float* ln2_g = (const float*)d_in[18];
    const float* ln2_b = (const float*)d_in[19];

    float* out = (float*)d_out;
    float* out_attn = out + (long long)BB * SS * DD;

    float *pwq, *pwk, *pwv, *pq, *pk, *pv, *pscores, *pconcat, *pffn1;
    cudaGetSymbolAddress((void**)&pwq, g_wq);
    cudaGetSymbolAddress((void**)&pwk, g_wk);
    cudaGetSymbolAddress((void**)&pwv, g_wv);
    cudaGetSymbolAddress((void**)&pq, g_q);
    cudaGetSymbolAddress((void**)&pk, g_k);
    cudaGetSymbolAddress((void**)&pv, g_v);
    cudaGetSymbolAddress((void**)&pscores, g_scores);
    cudaGetSymbolAddress((void**)&pconcat, g_concat);
    cudaGetSymbolAddress((void**)&pffn1, g_ffn1);

    const long long SD  = (long long)SS * DD;        // per-batch stride of [B,S,D]
    const long long SSq = (long long)SS * SS;        // per-head stride of scores
    dim3 blk(256);
    const int MT = BB * SS;                          // 4096 token rows

    // repack per-head projection weights into [D, D]
    repack_kernel<<<(DD * DD) / 256, 256>>>(wq, wk, wv);

    // q/k/v projections: [4096,1024] @ [1024,1024] + bias
    gemm_tc<128, 128, 0, 0><<<dim3(8, 32, 1), blk>>>(x_q, pwq, bq, pq,
        DD, DD, DD, DD, 1, 0, 0, 0, 0, 0, 0, 1.0f);
    gemm_tc<128, 128, 0, 0><<<dim3(8, 32, 1), blk>>>(x_k, pwk, bk, pk,
        DD, DD, DD, DD, 1, 0, 0, 0, 0, 0, 0, 1.0f);
    gemm_tc<128, 128, 0, 0><<<dim3(8, 32, 1), blk>>>(x_v, pwv, bv, pv,
        DD, DD, DD, DD, 1, 0, 0, 0, 0, 0, 0, 1.0f);

    // scores = Q K^T / sqrt(DK), batched over B*H
    gemm_tc<128, 128, 1, 0><<<dim3(8, 8, BB * HH), blk>>>(pq, pk, nullptr, pscores,
        DK, DD, DD, SS,
        HH, DK, SD, DK, SD, SSq, (long long)HH * SSq, 0.125f);

    // softmax (+mask) in place; last head -> d_out second half
    softmax_kernel<<<BB * HH * SS, blk>>>(pscores, mask, out_attn);

    // attn @ V -> concat [B,S,H*DK]
    gemm_tc<128, 64, 0, 0><<<dim3(1, 8, BB * HH), blk>>>(pscores, pv, nullptr, pconcat,
        SS, SS, DD, DD,
        HH, SSq, (long long)HH * SSq, DK, SD, DK, SD, 1.0f);

    // mha_out = concat @ w0 + b0   (reuse g_q)
    gemm_tc<128, 128, 0, 0><<<dim3(8, 32, 1), blk>>>(pconcat, w0, b0, pq,
        DD, DD, DD, DD, 1, 0, 0, 0, 0, 0, 0, 1.0f);

    // sub1 = LN1(x_q + mha_out)    (reuse g_k)
    add_ln_kernel<<<MT, blk>>>(x_q, pq, ln1_g, ln1_b, pk);

    // ffn1 = relu(sub1 @ ff1_w + ff1_b)
    gemm_tc<128, 128, 0, 1><<<dim3(32, 32, 1), blk>>>(pk, ff1_w, ff1_b, pffn1,
        DD, DD, DFF, DFF, 1, 0, 0, 0, 0, 0, 0, 1.0f);

    // ffn2 = ffn1 @ ff2_w + ff2_b  (reuse g_v)
    gemm_tc<128, 128, 0, 0><<<dim3(8, 32, 1), blk>>>(pffn1, ff2_w, ff2_b, pv,
        DFF, DFF, DD, DD, 1, 0, 0, 0, 0, 0, 0, 1.0f);

    // out = LN2(sub1 + ffn2) -> d_out first half
    add_ln_kernel<<<MT, blk>>>(pk, pv, ln2_g, ln2_b, out);
}

// round 3
// speedup vs baseline: 3.3395x; 1.2848x over previous
#include <cuda_runtime.h>
#include <math.h>
#include <stdint.h>

#define BB 4
#define SS 1024
#define DD 1024
#define HH 16
#define DK 64
#define DFF 4096

// ---------------- scratch (device globals; no allocations allowed) ----------
__device__ float g_wq[DD * DD];
__device__ float g_wk[DD * DD];
__device__ float g_wv[DD * DD];
__device__ float g_q[BB * SS * DD];       // q [B,S,H,DK]; reused as mha_out
__device__ float g_k[BB * SS * DD];       // k [B,S,H,DK]; reused as sub1
__device__ float g_v[BB * SS * DD];       // v [B,S,H,DK]; reused as ffn2 out
__device__ float g_scores[(long long)BB * HH * SS * SS]; // 256 MB
__device__ float g_concat[BB * SS * DD];
__device__ float g_ffn1[(long long)BB * SS * DFF];

// ---------------- helpers ----------------------------------------------------
__device__ __forceinline__ void cp16(float* smem_dst, const float* gmem_src) {
    uint32_t s = (uint32_t)__cvta_generic_to_shared(smem_dst);
    asm volatile("cp.async.ca.shared.global [%0], [%1], 16;" :: "r"(s), "l"(gmem_src));
}
__device__ __forceinline__ void cp_commit() {
    asm volatile("cp.async.commit_group;");
}
template <int N>
__device__ __forceinline__ void cp_wait() {
    asm volatile("cp.async.wait_group %0;" :: "n"(N));
}

__device__ __forceinline__ void mma8(float* d, const uint32_t* a, const uint32_t* b) {
    asm volatile(
        "mma.sync.aligned.m16n8k8.row.col.f32.tf32.tf32.f32 "
        "{%0,%1,%2,%3}, {%4,%5,%6,%7}, {%8,%9}, {%0,%1,%2,%3};"
        : "+f"(d[0]), "+f"(d[1]), "+f"(d[2]), "+f"(d[3])
        : "r"(a[0]), "r"(a[1]), "r"(a[2]), "r"(a[3]), "r"(b[0]), "r"(b[1]));
}

// ---------------- repack per-head weights [H,D,DK] -> [D, H*DK] -------------
__global__ void repack_kernel(const float* __restrict__ wq,
                              const float* __restrict__ wk,
                              const float* __restrict__ wv) {
    int idx = blockIdx.x * 256 + threadIdx.x;     // over D*D
    int d = idx >> 10;
    int c = idx & 1023;                            // c = h*DK + k
    int src = ((c >> 6) << 16) | (d << 6) | (c & 63); // h*D*DK + d*DK + k
    g_wq[idx] = wq[src];
    g_wk[idx] = wk[src];
    g_wv[idx] = wv[src];
}

// ---------------- TF32 tensor-core GEMM, cp.async double-buffered -----------
// C = alpha * A @ B (+bias) (+relu). Batch z = bz*Hn + hz, separate h/b strides.
// Block tile BM x BN, BK=32. 8 warps (2 x 4), warp tile (BM/2) x (BN/4).
// SMEM: A as [m][k] stride 36; B as [k][n] stride BN+8, or [n][k] stride 36
// when TRANSB (so cp.async 16B chunks stay contiguous). All conflict-free.
template <int BM, int BN, int TRANSB, int RELU>
__global__ __launch_bounds__(256, 2) void gemm_tc2(
    const float* __restrict__ A, const float* __restrict__ Bm,
    const float* __restrict__ bias, float* __restrict__ C,
    int K, int lda, int ldb, int ldc,
    int Hn, long long sAh, long long sAb, long long sBh, long long sBb,
    long long sCh, long long sCb, float alpha) {
    constexpr int BK = 32;
    constexpr int AST = BK + 4;                       // 36
    constexpr int BST = TRANSB ? (BK + 4) : (BN + 8); // [n][k] : [k][n]
    constexpr int BROWS = TRANSB ? BN : BK;
    constexpr int WM = BM / 2, WN = BN / 4;
    constexpr int MT = WM / 16, NT = WN / 8;
    constexpr int AV = BM * BK / 1024;   // 16B cp.async per thread, A tile
    constexpr int BV = BK * BN / 1024;   // 16B cp.async per thread, B tile

    extern __shared__ float sm[];
    float* Abase = sm;                        // [2][BM][AST]
    float* Bbase = sm + 2 * BM * AST;         // [2][BROWS][BST]

    int z = blockIdx.z;
    int hz = z % Hn, bz = z / Hn;
    A  += (long long)hz * sAh + (long long)bz * sAb;
    Bm += (long long)hz * sBh + (long long)bz * sBb;
    C  += (long long)hz * sCh + (long long)bz * sCb;

    const int tid = threadIdx.x;
    const int lane = tid & 31, warp = tid >> 5;
    const int wrow = warp >> 2, wcol = warp & 3;
    const int row0 = blockIdx.y * BM, col0 = blockIdx.x * BN;
    const int nk = K / BK;

    auto issue = [&](int kt) {
        float* as = Abase + (kt & 1) * BM * AST;
        float* bs = Bbase + (kt & 1) * BROWS * BST;
        #pragma unroll
        for (int i = 0; i < AV; i++) {
            int idx = tid + 256 * i;
            int m = idx >> 3, c4 = (idx & 7) * 4;
            cp16(as + m * AST + c4, A + (long long)(row0 + m) * lda + kt * BK + c4);
        }
        if (TRANSB) {
            #pragma unroll
            for (int i = 0; i < BV; i++) {
                int idx = tid + 256 * i;
                int n = idx >> 3, c4 = (idx & 7) * 4;
                cp16(bs + n * BST + c4, Bm + (long long)(col0 + n) * ldb + kt * BK + c4);
            }
        } else {
            #pragma unroll
            for (int i = 0; i < BV; i++) {
                int idx = tid + 256 * i;
                int kk = idx / (BN / 4), c4 = (idx % (BN / 4)) * 4;
                cp16(bs + kk * BST + c4, Bm + (long long)(kt * BK + kk) * ldb + col0 + c4);
            }
        }
        cp_commit();
    };

    float acc[MT][NT][4] = {};

    issue(0);
    if (nk > 1) issue(1);

    const int r = lane >> 2, c = lane & 3;
    for (int kt = 0; kt < nk; kt++) {
        if (kt == nk - 1) cp_wait<0>(); else cp_wait<1>();
        __syncthreads();

        const float* as = Abase + (kt & 1) * BM * AST;
        const float* bs = Bbase + (kt & 1) * BROWS * BST;
        #pragma unroll
        for (int ks = 0; ks < 4; ks++) {
            const int k0 = ks * 8;
            uint32_t af[MT][4], bf[NT][2];
            #pragma unroll
            for (int mt = 0; mt < MT; mt++) {
                int m = wrow * WM + mt * 16 + r;
                af[mt][0] = *(const uint32_t*)&as[m * AST + k0 + c];
                af[mt][1] = *(const uint32_t*)&as[(m + 8) * AST + k0 + c];
                af[mt][2] = *(const uint32_t*)&as[m * AST + k0 + c + 4];
                af[mt][3] = *(const uint32_t*)&as[(m + 8) * AST + k0 + c + 4];
            }
            #pragma unroll
            for (int nt = 0; nt < NT; nt++) {
                int n = wcol * WN + nt * 8 + r;
                if (TRANSB) {
                    bf[nt][0] = *(const uint32_t*)&bs[n * BST + k0 + c];
                    bf[nt][1] = *(const uint32_t*)&bs[n * BST + k0 + c + 4];
                } else {
                    bf[nt][0] = *(const uint32_t*)&bs[(k0 + c) * BST + n];
                    bf[nt][1] = *(const uint32_t*)&bs[(k0 + c + 4) * BST + n];
                }
            }
            #pragma unroll
            for (int mt = 0; mt < MT; mt++)
                #pragma unroll
                for (int nt = 0; nt < NT; nt++)
                    mma8(acc[mt][nt], af[mt], bf[nt]);
        }
        __syncthreads();
        if (kt + 2 < nk) issue(kt + 2);
    }

    // epilogue
    const int c2 = (lane & 3) * 2;
    #pragma unroll
    for (int mt = 0; mt < MT; mt++) {
        int mrow = row0 + wrow * WM + mt * 16 + r;
        #pragma unroll
        for (int nt = 0; nt < NT; nt++) {
            int ncol = col0 + wcol * WN + nt * 8 + c2;
            float b0 = 0.0f, b1 = 0.0f;
            if (bias) { b0 = bias[ncol]; b1 = bias[ncol + 1]; }
            float v0 = acc[mt][nt][0] * alpha + b0;
            float v1 = acc[mt][nt][1] * alpha + b1;
            float v2 = acc[mt][nt][2] * alpha + b0;
            float v3 = acc[mt][nt][3] * alpha + b1;
            if (RELU) {
                v0 = fmaxf(v0, 0.0f); v1 = fmaxf(v1, 0.0f);
                v2 = fmaxf(v2, 0.0f); v3 = fmaxf(v3, 0.0f);
            }
            *(float2*)(C + (long long)mrow * ldc + ncol) = make_float2(v0, v1);
            *(float2*)(C + (long long)(mrow + 8) * ldc + ncol) = make_float2(v2, v3);
        }
    }
}

// ---------------- softmax over rows of g_scores; emits last head -----------
__global__ __launch_bounds__(256) void softmax_kernel(
    float* __restrict__ scores, const float* __restrict__ mask,
    float* __restrict__ out_attn) {
    long long r = blockIdx.x;               // 0 .. B*H*S-1
    int s = (int)(r & (SS - 1));
    int h = (int)((r >> 10) & (HH - 1));
    int b = (int)(r >> 14);
    float* row = scores + r * SS;
    const float* mrow = mask + (long long)b * SS;
    int tid = threadIdx.x;

    float vals[4];
    float mx = -1e30f;
    #pragma unroll
    for (int i = 0; i < 4; i++) {
        int t = tid + 256 * i;
        float v = row[t] + mrow[t] * (-1e9f);
        vals[i] = v;
        mx = fmaxf(mx, v);
    }
    __shared__ float red[256];
    red[tid] = mx;
    __syncthreads();
    for (int off = 128; off > 0; off >>= 1) {
        if (tid < off) red[tid] = fmaxf(red[tid], red[tid + off]);
        __syncthreads();
    }
    mx = red[0];
    __syncthreads();

    float sum = 0.0f;
    #pragma unroll
    for (int i = 0; i < 4; i++) {
        vals[i] = __expf(vals[i] - mx);
        sum += vals[i];
    }
    red[tid] = sum;
    __syncthreads();
    for (int off = 128; off > 0; off >>= 1) {
        if (tid < off) red[tid] += red[tid + off];
        __syncthreads();
    }
    float inv = 1.0f / red[0];

    #pragma unroll
    for (int i = 0; i < 4; i++) {
        int t = tid + 256 * i;
        float p = vals[i] * inv;
        row[t] = p;
        if (h == HH - 1)
            out_attn[((long long)(b * SS + s)) * SS + t] = p;
    }
}

// ---------------- residual add + layernorm ---------------------------------
__global__ __launch_bounds__(256) void add_ln_kernel(
    const float* __restrict__ xa, const float* __restrict__ xb,
    const float* __restrict__ g, const float* __restrict__ bt,
    float* __restrict__ out) {
    long long r = blockIdx.x;               // 0 .. B*S-1
    const float* pa = xa + r * DD;
    const float* pb = xb + r * DD;
    float* po = out + r * DD;
    int tid = threadIdx.x;

    float v[4];
    float sum = 0.0f, sq = 0.0f;
    #pragma unroll
    for (int i = 0; i < 4; i++) {
        int c = tid + 256 * i;
        float x = pa[c] + pb[c];
        v[i] = x;
        sum += x;
        sq += x * x;
    }
    __shared__ float r1[256], r2[256];
    r1[tid] = sum;
    r2[tid] = sq;
    __syncthreads();
    for (int off = 128; off > 0; off >>= 1) {
        if (tid < off) { r1[tid] += r1[tid + off]; r2[tid] += r2[tid + off]; }
        __syncthreads();
    }
    float mu = r1[0] * (1.0f / DD);
    float var = r2[0] * (1.0f / DD) - mu * mu;
    float rstd = rsqrtf(var + 1e-6f);

    #pragma unroll
    for (int i = 0; i < 4; i++) {
        int c = tid + 256 * i;
        po[c] = (v[i] - mu) * rstd * g[c] + bt[c];
    }
}

// ---------------- launch ----------------------------------------------------
static int g_smem_set = 0;

extern "C" void kernel_launch(void* const* d_in, const int* in_sizes, int n_in,
                              void* d_out, int out_size) {
    const float* x_v   = (const float*)d_in[0];
    const float* x_k   = (const float*)d_in[1];
    const float* x_q   = (const float*)d_in[2];
    const float* mask  = (const float*)d_in[3];
    const float* wq    = (const float*)d_in[4];
    const float* bq    = (const float*)d_in[5];
    const float* wk    = (const float*)d_in[6];
    const float* bk    = (const float*)d_in[7];
    const float* wv    = (const float*)d_in[8];
    const float* bv    = (const float*)d_in[9];
    const float* w0    = (const float*)d_in[10];
    const float* b0    = (const float*)d_in[11];
    const float* ln1_g = (const float*)d_in[12];
    const float* ln1_b = (const float*)d_in[13];
    const float* ff1_w = (const float*)d_in[14];
    const float* ff1_b = (const float*)d_in[15];
    const float* ff2_w = (const float*)d_in[16];
    const float* ff2_b = (const float*)d_in[17];
    const float* ln2_g = (const float*)d_in[18];
    const float* ln2_b = (const float*)d_in[19];

    float* out = (float*)d_out;
    float* out_attn = out + (long long)BB * SS * DD;

    // dynamic smem sizes per instantiation
    const int SM_NN = 2 * (128 * 36 + 32 * 136) * 4;   // 71680  <128,128,0,*>
    const int SM_TR = 2 * (128 * 36 + 128 * 36) * 4;   // 73728  <128,128,1,0>
    const int SM_AV = 2 * (128 * 36 + 32 * 72) * 4;    // 55296  <128,64,0,0>

    if (!g_smem_set) {
        cudaFuncSetAttribute(gemm_tc2<128, 128, 0, 0>,
                             cudaFuncAttributeMaxDynamicSharedMemorySize, SM_NN);
        cudaFuncSetAttribute(gemm_tc2<128, 128, 0, 1>,
                             cudaFuncAttributeMaxDynamicSharedMemorySize, SM_NN);
        cudaFuncSetAttribute(gemm_tc2<128, 128, 1, 0>,
                             cudaFuncAttributeMaxDynamicSharedMemorySize, SM_TR);
        cudaFuncSetAttribute(gemm_tc2<128, 64, 0, 0>,
                             cudaFuncAttributeMaxDynamicSharedMemorySize, SM_AV);
        g_smem_set = 1;
    }

    float *pwq, *pwk, *pwv, *pq, *pk, *pv, *pscores, *pconcat, *pffn1;
    cudaGetSymbolAddress((void**)&pwq, g_wq);
    cudaGetSymbolAddress((void**)&pwk, g_wk);
    cudaGetSymbolAddress((void**)&pwv, g_wv);
    cudaGetSymbolAddress((void**)&pq, g_q);
    cudaGetSymbolAddress((void**)&pk, g_k);
    cudaGetSymbolAddress((void**)&pv, g_v);
    cudaGetSymbolAddress((void**)&pscores, g_scores);
    cudaGetSymbolAddress((void**)&pconcat, g_concat);
    cudaGetSymbolAddress((void**)&pffn1, g_ffn1);

    const long long SD  = (long long)SS * DD;        // per-batch stride of [B,S,D]
    const long long SSq = (long long)SS * SS;        // per-head stride of scores
    dim3 blk(256);
    const int MT = BB * SS;                          // 4096 token rows

    // repack per-head projection weights into [D, D]
    repack_kernel<<<(DD * DD) / 256, 256>>>(wq, wk, wv);

    // q/k/v projections: [4096,1024] @ [1024,1024] + bias
    gemm_tc2<128, 128, 0, 0><<<dim3(8, 32, 1), blk, SM_NN>>>(x_q, pwq, bq, pq,
        DD, DD, DD, DD, 1, 0, 0, 0, 0, 0, 0, 1.0f);
    gemm_tc2<128, 128, 0, 0><<<dim3(8, 32, 1), blk, SM_NN>>>(x_k, pwk, bk, pk,
        DD, DD, DD, DD, 1, 0, 0, 0, 0, 0, 0, 1.0f);
    gemm_tc2<128, 128, 0, 0><<<dim3(8, 32, 1), blk, SM_NN>>>(x_v, pwv, bv, pv,
        DD, DD, DD, DD, 1, 0, 0, 0, 0, 0, 0, 1.0f);

    // scores = Q K^T / sqrt(DK), batched over B*H
    gemm_tc2<128, 128, 1, 0><<<dim3(8, 8, BB * HH), blk, SM_TR>>>(pq, pk, nullptr, pscores,
        DK, DD, DD, SS,
        HH, DK, SD, DK, SD, SSq, (long long)HH * SSq, 0.125f);

    // softmax (+mask) in place; last head -> d_out second half
    softmax_kernel<<<BB * HH * SS, blk>>>(pscores, mask, out_attn);

    // attn @ V -> concat [B,S,H*DK]
    gemm_tc2<128, 64, 0, 0><<<dim3(1, 8, BB * HH), blk, SM_AV>>>(pscores, pv, nullptr, pconcat,
        SS, SS, DD, DD,
        HH, SSq, (long long)HH * SSq, DK, SD, DK, SD, 1.0f);

    // mha_out = concat @ w0 + b0   (reuse g_q)
    gemm_tc2<128, 128, 0, 0><<<dim3(8, 32, 1), blk, SM_NN>>>(pconcat, w0, b0, pq,
        DD, DD, DD, DD, 1, 0, 0, 0, 0, 0, 0, 1.0f);

    // sub1 = LN1(x_q + mha_out)    (reuse g_k)
    add_ln_kernel<<<MT, blk>>>(x_q, pq, ln1_g, ln1_b, pk);

    // ffn1 = relu(sub1 @ ff1_w + ff1_b)
    gemm_tc2<128, 128, 0, 1><<<dim3(32, 32, 1), blk, SM_NN>>>(pk, ff1_w, ff1_b, pffn1,
        DD, DD, DFF, DFF, 1, 0, 0, 0, 0, 0, 0, 1.0f);

    // ffn2 = ffn1 @ ff2_w + ff2_b  (reuse g_v)
    gemm_tc2<128, 128, 0, 0><<<dim3(8, 32, 1), blk, SM_NN>>>(pffn1, ff2_w, ff2_b, pv,
        DFF, DFF, DD, DD, 1, 0, 0, 0, 0, 0, 0, 1.0f);

    // out = LN2(sub1 + ffn2) -> d_out first half
    add_ln_kernel<<<MT, blk>>>(pk, pv, ln2_g, ln2_b, out);
}

// round 4
// speedup vs baseline: 3.6849x; 1.1034x over previous
#include <cuda_runtime.h>
#include <math.h>
#include <stdint.h>

#define BB 4
#define SS 1024
#define DD 1024
#define HH 16
#define DK 64
#define DFF 4096

// ---------------- scratch (device globals; no allocations allowed) ----------
__device__ float g_xq[BB * SS * DD];      // rounded x_q; reused as mha_out
__device__ float g_xk[BB * SS * DD];      // rounded x_k; reused as sub1_rounded
__device__ float g_xv[BB * SS * DD];      // rounded x_v; reused as ffn2 out
__device__ float g_w0r[DD * DD];
__device__ float g_ff1r[DD * DFF];
__device__ float g_ff2r[DFF * DD];
__device__ float g_wq[DD * DD];
__device__ float g_wk[DD * DD];
__device__ float g_wv[DD * DD];
__device__ float g_q[BB * SS * DD];       // q [B,S,H,DK]
__device__ float g_k[BB * SS * DD];       // k; reused as sub1 (exact)
__device__ float g_v[BB * SS * DD];       // v
__device__ float g_att_raw[(long long)BB * SS * SS]; // last-head raw scores (16MB)
__device__ float g_concat[BB * SS * DD];  // flash O output
__device__ float g_ffn1[(long long)BB * SS * DFF];

// ---------------- helpers ----------------------------------------------------
__device__ __forceinline__ void cp16(float* smem_dst, const float* gmem_src) {
    uint32_t s = (uint32_t)__cvta_generic_to_shared(smem_dst);
    asm volatile("cp.async.ca.shared.global [%0], [%1], 16;" :: "r"(s), "l"(gmem_src));
}
__device__ __forceinline__ void cp_commit() {
    asm volatile("cp.async.commit_group;");
}
template <int N>
__device__ __forceinline__ void cp_wait() {
    asm volatile("cp.async.wait_group %0;" :: "n"(N));
}
__device__ __forceinline__ float rna(float x) {
    uint32_t u;
    asm("cvt.rna.tf32.f32 %0, %1;" : "=r"(u) : "f"(x));
    return __uint_as_float(u);
}
__device__ __forceinline__ void mma8(float* d, const uint32_t* a, const uint32_t* b) {
    asm volatile(
        "mma.sync.aligned.m16n8k8.row.col.f32.tf32.tf32.f32 "
        "{%0,%1,%2,%3}, {%4,%5,%6,%7}, {%8,%9}, {%0,%1,%2,%3};"
        : "+f"(d[0]), "+f"(d[1]), "+f"(d[2]), "+f"(d[3])
        : "r"(a[0]), "r"(a[1]), "r"(a[2]), "r"(a[3]), "r"(b[0]), "r"(b[1]));
}

// ---------------- prep: round-to-nearest tf32 copies -------------------------
__global__ void round_copy(const float* __restrict__ src, float* __restrict__ dst) {
    int i = blockIdx.x * 256 + threadIdx.x;
    float4 v = ((const float4*)src)[i];
    v.x = rna(v.x); v.y = rna(v.y); v.z = rna(v.z); v.w = rna(v.w);
    ((float4*)dst)[i] = v;
}

// repack per-head weights [H,D,DK] -> [D, H*DK], rounded
__global__ void repack_kernel(const float* __restrict__ wq,
                              const float* __restrict__ wk,
                              const float* __restrict__ wv) {
    int idx = blockIdx.x * 256 + threadIdx.x;     // over D*D
    int d = idx >> 10;
    int c = idx & 1023;                            // c = h*DK + k
    int src = ((c >> 6) << 16) | (d << 6) | (c & 63);
    g_wq[idx] = rna(wq[src]);
    g_wk[idx] = rna(wk[src]);
    g_wv[idx] = rna(wv[src]);
}

// ---------------- TF32 tensor-core GEMM, cp.async double-buffered -----------
template <int BM, int BN, int RELU, int RND>
__global__ __launch_bounds__(256, 2) void gemm_tc2(
    const float* __restrict__ A, const float* __restrict__ Bm,
    const float* __restrict__ bias, float* __restrict__ C,
    int K, int lda, int ldb, int ldc) {
    constexpr int BK = 32;
    constexpr int AST = BK + 4;                       // 36
    constexpr int BST = BN + 8;
    constexpr int WM = BM / 2, WN = BN / 4;
    constexpr int MT = WM / 16, NT = WN / 8;
    constexpr int AV = BM * BK / 1024;
    constexpr int BV = BK * BN / 1024;

    extern __shared__ float sm[];
    float* Abase = sm;                        // [2][BM][AST]
    float* Bbase = sm + 2 * BM * AST;         // [2][BK][BST]

    const int tid = threadIdx.x;
    const int lane = tid & 31, warp = tid >> 5;
    const int wrow = warp >> 2, wcol = warp & 3;
    const int row0 = blockIdx.y * BM, col0 = blockIdx.x * BN;
    const int nk = K / BK;

    auto issue = [&](int kt) {
        float* as = Abase + (kt & 1) * BM * AST;
        float* bs = Bbase + (kt & 1) * BK * BST;
        #pragma unroll
        for (int i = 0; i < AV; i++) {
            int idx = tid + 256 * i;
            int m = idx >> 3, c4 = (idx & 7) * 4;
            cp16(as + m * AST + c4, A + (long long)(row0 + m) * lda + kt * BK + c4);
        }
        #pragma unroll
        for (int i = 0; i < BV; i++) {
            int idx = tid + 256 * i;
            int kk = idx / (BN / 4), c4 = (idx % (BN / 4)) * 4;
            cp16(bs + kk * BST + c4, Bm + (long long)(kt * BK + kk) * ldb + col0 + c4);
        }
        cp_commit();
    };

    float acc[MT][NT][4] = {};

    issue(0);
    if (nk > 1) issue(1);

    const int r = lane >> 2, c = lane & 3;
    for (int kt = 0; kt < nk; kt++) {
        if (kt == nk - 1) cp_wait<0>(); else cp_wait<1>();
        __syncthreads();

        const float* as = Abase + (kt & 1) * BM * AST;
        const float* bs = Bbase + (kt & 1) * BK * BST;
        #pragma unroll
        for (int ks = 0; ks < 4; ks++) {
            const int k0 = ks * 8;
            uint32_t af[MT][4], bf[NT][2];
            #pragma unroll
            for (int mt = 0; mt < MT; mt++) {
                int m = wrow * WM + mt * 16 + r;
                af[mt][0] = *(const uint32_t*)&as[m * AST + k0 + c];
                af[mt][1] = *(const uint32_t*)&as[(m + 8) * AST + k0 + c];
                af[mt][2] = *(const uint32_t*)&as[m * AST + k0 + c + 4];
                af[mt][3] = *(const uint32_t*)&as[(m + 8) * AST + k0 + c + 4];
            }
            #pragma unroll
            for (int nt = 0; nt < NT; nt++) {
                int n = wcol * WN + nt * 8 + r;
                bf[nt][0] = *(const uint32_t*)&bs[(k0 + c) * BST + n];
                bf[nt][1] = *(const uint32_t*)&bs[(k0 + c + 4) * BST + n];
            }
            #pragma unroll
            for (int mt = 0; mt < MT; mt++)
                #pragma unroll
                for (int nt = 0; nt < NT; nt++)
                    mma8(acc[mt][nt], af[mt], bf[nt]);
        }
        __syncthreads();
        if (kt + 2 < nk) issue(kt + 2);
    }

    const int c2 = (lane & 3) * 2;
    #pragma unroll
    for (int mt = 0; mt < MT; mt++) {
        int mrow = row0 + wrow * WM + mt * 16 + r;
        #pragma unroll
        for (int nt = 0; nt < NT; nt++) {
            int ncol = col0 + wcol * WN + nt * 8 + c2;
            float b0 = 0.0f, b1 = 0.0f;
            if (bias) { b0 = bias[ncol]; b1 = bias[ncol + 1]; }
            float v0 = acc[mt][nt][0] + b0;
            float v1 = acc[mt][nt][1] + b1;
            float v2 = acc[mt][nt][2] + b0;
            float v3 = acc[mt][nt][3] + b1;
            if (RELU) {
                v0 = fmaxf(v0, 0.0f); v1 = fmaxf(v1, 0.0f);
                v2 = fmaxf(v2, 0.0f); v3 = fmaxf(v3, 0.0f);
            }
            if (RND) {
                v0 = rna(v0); v1 = rna(v1); v2 = rna(v2); v3 = rna(v3);
            }
            *(float2*)(C + (long long)mrow * ldc + ncol) = make_float2(v0, v1);
            *(float2*)(C + (long long)(mrow + 8) * ldc + ncol) = make_float2(v2, v3);
        }
    }
}

// ---------------- fused flash attention -------------------------------------
// grid (S/128, B*H). One CTA: 128 Q rows x one head. 16 KV steps of 64 rows.
__global__ __launch_bounds__(256, 1) void flash_attn(
    const float* __restrict__ Q, const float* __restrict__ K,
    const float* __restrict__ V, const float* __restrict__ mask,
    float* __restrict__ Oc, float* __restrict__ raw15) {
    constexpr int QST = 68, KST = 68, VST = 72, PST = 68;
    extern __shared__ float sm[];
    float* Qs   = sm;                       // 128*68
    float* Ksb  = Qs + 128 * QST;           // 2*64*68
    float* Vsb  = Ksb + 2 * 64 * KST;       // 2*64*72
    float* Ps   = Vsb + 2 * 64 * VST;       // 128*68
    float* Msk  = Ps + 128 * PST;           // 1024
    float* red0 = Msk + 1024;               // 128*4
    float* red1 = red0 + 512;               // 128*4

    const int qb = blockIdx.x, bh = blockIdx.y;
    const int b = bh >> 4, h = bh & 15;
    const float* qp = Q + ((long long)(b * SS + qb * 128)) * DD + h * 64;
    const float* kp = K + ((long long)b * SS) * DD + h * 64;
    const float* vp = V + ((long long)b * SS) * DD + h * 64;
    const float* mp = mask + b * SS;

    const int tid = threadIdx.x, lane = tid & 31, warp = tid >> 5;
    const int wrow = warp >> 2, wcol = warp & 3;
    const int r = lane >> 2, c = lane & 3;

    // prologue loads: mask row, Q tile, KV stage 0
    cp16(Msk + tid * 4, mp + tid * 4);
    #pragma unroll
    for (int i = 0; i < 8; i++) {
        int idx = tid + 256 * i;
        int m = idx >> 4, c4 = (idx & 15) * 4;
        cp16(Qs + m * QST + c4, qp + (long long)m * DD + c4);
    }
    #pragma unroll
    for (int i = 0; i < 4; i++) {
        int idx = tid + 256 * i;
        int n = idx >> 4, c4 = (idx & 15) * 4;
        cp16(Ksb + n * KST + c4, kp + (long long)n * DD + c4);
        cp16(Vsb + n * VST + c4, vp + (long long)n * DD + c4);
    }
    cp_commit();

    float acc_o[4][2][4] = {};
    float mprev[4][2], lsum[4][2];
    #pragma unroll
    for (int mt = 0; mt < 4; mt++)
        #pragma unroll
        for (int hf = 0; hf < 2; hf++) { mprev[mt][hf] = -1e30f; lsum[mt][hf] = 0.0f; }

    for (int j = 0; j < 16; j++) {
        cp_wait<0>();
        __syncthreads();
        const float* ks = Ksb + (j & 1) * 64 * KST;
        const float* vs = Vsb + (j & 1) * 64 * VST;

        // S = Q @ K^T
        float sv[4][2][4] = {};
        #pragma unroll
        for (int k0 = 0; k0 < 64; k0 += 8) {
            uint32_t af[4][4], bf[2][2];
            #pragma unroll
            for (int mt = 0; mt < 4; mt++) {
                int m = wrow * 64 + mt * 16 + r;
                af[mt][0] = *(const uint32_t*)&Qs[m * QST + k0 + c];
                af[mt][1] = *(const uint32_t*)&Qs[(m + 8) * QST + k0 + c];
                af[mt][2] = *(const uint32_t*)&Qs[m * QST + k0 + c + 4];
                af[mt][3] = *(const uint32_t*)&Qs[(m + 8) * QST + k0 + c + 4];
            }
            #pragma unroll
            for (int nt = 0; nt < 2; nt++) {
                int n = wcol * 16 + nt * 8 + r;
                bf[nt][0] = *(const uint32_t*)&ks[n * KST + k0 + c];
                bf[nt][1] = *(const uint32_t*)&ks[n * KST + k0 + c + 4];
            }
            #pragma unroll
            for (int mt = 0; mt < 4; mt++)
                #pragma unroll
                for (int nt = 0; nt < 2; nt++)
                    mma8(sv[mt][nt], af[mt], bf[nt]);
        }

        // scale + mask
        float mk[2][2];
        #pragma unroll
        for (int nt = 0; nt < 2; nt++)
            #pragma unroll
            for (int j2 = 0; j2 < 2; j2++)
                mk[nt][j2] = Msk[j * 64 + wcol * 16 + nt * 8 + 2 * c + j2] * (-1e9f);
        #pragma unroll
        for (int mt = 0; mt < 4; mt++)
            #pragma unroll
            for (int nt = 0; nt < 2; nt++)
                #pragma unroll
                for (int i = 0; i < 4; i++)
                    sv[mt][nt][i] = sv[mt][nt][i] * 0.125f + mk[nt][i & 1];

        // raw score dump for the last head (feeds attn_w output)
        if (h == HH - 1) {
            #pragma unroll
            for (int mt = 0; mt < 4; mt++)
                #pragma unroll
                for (int hf = 0; hf < 2; hf++) {
                    int grow = b * SS + qb * 128 + wrow * 64 + mt * 16 + r + 8 * hf;
                    #pragma unroll
                    for (int nt = 0; nt < 2; nt++) {
                        int col = j * 64 + wcol * 16 + nt * 8 + 2 * c;
                        *(float2*)(raw15 + (long long)grow * SS + col) =
                            make_float2(sv[mt][nt][2 * hf], sv[mt][nt][2 * hf + 1]);
                    }
                }
        }

        // phase A: block row max
        float mnew[4][2];
        #pragma unroll
        for (int mt = 0; mt < 4; mt++)
            #pragma unroll
            for (int hf = 0; hf < 2; hf++) {
                float v = fmaxf(fmaxf(sv[mt][0][2 * hf], sv[mt][0][2 * hf + 1]),
                                fmaxf(sv[mt][1][2 * hf], sv[mt][1][2 * hf + 1]));
                v = fmaxf(v, __shfl_xor_sync(0xffffffffu, v, 1));
                v = fmaxf(v, __shfl_xor_sync(0xffffffffu, v, 2));
                if (c == 0)
                    red0[(wrow * 64 + mt * 16 + r + 8 * hf) * 4 + wcol] = v;
            }
        __syncthreads();
        #pragma unroll
        for (int mt = 0; mt < 4; mt++)
            #pragma unroll
            for (int hf = 0; hf < 2; hf++) {
                int row = wrow * 64 + mt * 16 + r + 8 * hf;
                float mc = fmaxf(fmaxf(red0[row * 4 + 0], red0[row * 4 + 1]),
                                 fmaxf(red0[row * 4 + 2], red0[row * 4 + 3]));
                mnew[mt][hf] = fmaxf(mprev[mt][hf], mc);
            }

        // prefetch next KV stage
        if (j + 1 < 16) {
            float* kd = Ksb + ((j + 1) & 1) * 64 * KST;
            float* vd = Vsb + ((j + 1) & 1) * 64 * VST;
            #pragma unroll
            for (int i = 0; i < 4; i++) {
                int idx = tid + 256 * i;
                int n = idx >> 4, c4 = (idx & 15) * 4;
                cp16(kd + n * KST + c4, kp + (long long)((j + 1) * 64 + n) * DD + c4);
                cp16(vd + n * VST + c4, vp + (long long)((j + 1) * 64 + n) * DD + c4);
            }
            cp_commit();
        }

        // phase B: exp, row sums, P -> SMEM (tf32-rounded)
        float psum[4][2] = {};
        #pragma unroll
        for (int mt = 0; mt < 4; mt++)
            #pragma unroll
            for (int nt = 0; nt < 2; nt++)
                #pragma unroll
                for (int i = 0; i < 4; i++) {
                    float p = __expf(sv[mt][nt][i] - mnew[mt][i >> 1]);
                    sv[mt][nt][i] = p;
                    psum[mt][i >> 1] += p;
                }
        #pragma unroll
        for (int mt = 0; mt < 4; mt++)
            #pragma unroll
            for (int hf = 0; hf < 2; hf++) {
                float v = psum[mt][hf];
                v += __shfl_xor_sync(0xffffffffu, v, 1);
                v += __shfl_xor_sync(0xffffffffu, v, 2);
                if (c == 0)
                    red1[(wrow * 64 + mt * 16 + r + 8 * hf) * 4 + wcol] = v;
            }
        #pragma unroll
        for (int mt = 0; mt < 4; mt++)
            #pragma unroll
            for (int hf = 0; hf < 2; hf++) {
                int row = wrow * 64 + mt * 16 + r + 8 * hf;
                #pragma unroll
                for (int nt = 0; nt < 2; nt++) {
                    int col = wcol * 16 + nt * 8 + 2 * c;
                    *(float2*)&Ps[row * PST + col] =
                        make_float2(rna(sv[mt][nt][2 * hf]), rna(sv[mt][nt][2 * hf + 1]));
                }
            }
        __syncthreads();

        // finalize stats, rescale O
        #pragma unroll
        for (int mt = 0; mt < 4; mt++)
            #pragma unroll
            for (int hf = 0; hf < 2; hf++) {
                int row = wrow * 64 + mt * 16 + r + 8 * hf;
                float sumb = red1[row * 4 + 0] + red1[row * 4 + 1] +
                             red1[row * 4 + 2] + red1[row * 4 + 3];
                float alpha = __expf(mprev[mt][hf] - mnew[mt][hf]);
                lsum[mt][hf] = lsum[mt][hf] * alpha + sumb;
                mprev[mt][hf] = mnew[mt][hf];
                #pragma unroll
                for (int nt = 0; nt < 2; nt++) {
                    acc_o[mt][nt][2 * hf] *= alpha;
                    acc_o[mt][nt][2 * hf + 1] *= alpha;
                }
            }

        // O += P @ V
        #pragma unroll
        for (int k0 = 0; k0 < 64; k0 += 8) {
            uint32_t af[4][4], bf[2][2];
            #pragma unroll
            for (int mt = 0; mt < 4; mt++) {
                int m = wrow * 64 + mt * 16 + r;
                af[mt][0] = *(const uint32_t*)&Ps[m * PST + k0 + c];
                af[mt][1] = *(const uint32_t*)&Ps[(m + 8) * PST + k0 + c];
                af[mt][2] = *(const uint32_t*)&Ps[m * PST + k0 + c + 4];
                af[mt][3] = *(const uint32_t*)&Ps[(m + 8) * PST + k0 + c + 4];
            }
            #pragma unroll
            for (int nt = 0; nt < 2; nt++) {
                int n = wcol * 16 + nt * 8 + r;
                bf[nt][0] = *(const uint32_t*)&vs[(k0 + c) * VST + n];
                bf[nt][1] = *(const uint32_t*)&vs[(k0 + c + 4) * VST + n];
            }
            #pragma unroll
            for (int mt = 0; mt < 4; mt++)
                #pragma unroll
                for (int nt = 0; nt < 2; nt++)
                    mma8(acc_o[mt][nt], af[mt], bf[nt]);
        }
    }

    // epilogue: O / l -> concat (rounded, feeds w0 GEMM)
    #pragma unroll
    for (int mt = 0; mt < 4; mt++) {
        #pragma unroll
        for (int hf = 0; hf < 2; hf++) {
            float inv = 1.0f / lsum[mt][hf];
            int grow = b * SS + qb * 128 + wrow * 64 + mt * 16 + r + 8 * hf;
            #pragma unroll
            for (int nt = 0; nt < 2; nt++) {
                int col = h * 64 + wcol * 16 + nt * 8 + 2 * c;
                *(float2*)(Oc + (long long)grow * DD + col) =
                    make_float2(rna(acc_o[mt][nt][2 * hf] * inv),
                                rna(acc_o[mt][nt][2 * hf + 1] * inv));
            }
        }
    }
}

// ---------------- softmax of dumped last-head scores -> out_attn -----------
__global__ __launch_bounds__(256) void softmax_out(
    const float* __restrict__ raw, float* __restrict__ out_attn) {
    long long rr = blockIdx.x;               // 0 .. B*S-1
    const float* row = raw + rr * SS;
    float* orow = out_attn + rr * SS;
    int tid = threadIdx.x;

    float vals[4];
    float mx = -1e30f;
    #pragma unroll
    for (int i = 0; i < 4; i++) {
        float v = row[tid + 256 * i];
        vals[i] = v;
        mx = fmaxf(mx, v);
    }
    __shared__ float red[256];
    red[tid] = mx;
    __syncthreads();
    for (int off = 128; off > 0; off >>= 1) {
        if (tid < off) red[tid] = fmaxf(red[tid], red[tid + off]);
        __syncthreads();
    }
    mx = red[0];
    __syncthreads();
    float sum = 0.0f;
    #pragma unroll
    for (int i = 0; i < 4; i++) {
        vals[i] = __expf(vals[i] - mx);
        sum += vals[i];
    }
    red[tid] = sum;
    __syncthreads();
    for (int off = 128; off > 0; off >>= 1) {
        if (tid < off) red[tid] += red[tid + off];
        __syncthreads();
    }
    float inv = 1.0f / red[0];
    #pragma unroll
    for (int i = 0; i < 4; i++)
        orow[tid + 256 * i] = vals[i] * inv;
}

// ---------------- residual add + layernorm (optional rounded copy) ---------
__global__ __launch_bounds__(256) void add_ln_kernel(
    const float* __restrict__ xa, const float* __restrict__ xb,
    const float* __restrict__ g, const float* __restrict__ bt,
    float* __restrict__ out, float* __restrict__ out_r) {
    long long rr = blockIdx.x;               // 0 .. B*S-1
    const float* pa = xa + rr * DD;
    const float* pb = xb + rr * DD;
    float* po = out + rr * DD;
    int tid = threadIdx.x;

    float v[4];
    float sum = 0.0f, sq = 0.0f;
    #pragma unroll
    for (int i = 0; i < 4; i++) {
        int cc = tid + 256 * i;
        float x = pa[cc] + pb[cc];
        v[i] = x;
        sum += x;
        sq += x * x;
    }
    __shared__ float r1[256], r2[256];
    r1[tid] = sum;
    r2[tid] = sq;
    __syncthreads();
    for (int off = 128; off > 0; off >>= 1) {
        if (tid < off) { r1[tid] += r1[tid + off]; r2[tid] += r2[tid + off]; }
        __syncthreads();
    }
    float mu = r1[0] * (1.0f / DD);
    float var = r2[0] * (1.0f / DD) - mu * mu;
    float rstd = rsqrtf(var + 1e-6f);

    #pragma unroll
    for (int i = 0; i < 4; i++) {
        int cc = tid + 256 * i;
        float y = (v[i] - mu) * rstd * g[cc] + bt[cc];
        po[cc] = y;
        if (out_r) out_r[rr * DD + cc] = rna(y);
    }
}

// ---------------- launch ----------------------------------------------------
static int g_attr_set = 0;

extern "C" void kernel_launch(void* const* d_in, const int* in_sizes, int n_in,
                              void* d_out, int out_size) {
    const float* x_v   = (const float*)d_in[0];
    const float* x_k   = (const float*)d_in[1];
    const float* x_q   = (const float*)d_in[2];
    const float* mask  = (const float*)d_in[3];
    const float* wq    = (const float*)d_in[4];
    const float* bq    = (const float*)d_in[5];
    const float* wk    = (const float*)d_in[6];
    const float* bk    = (const float*)d_in[7];
    const float* wv    = (const float*)d_in[8];
    const float* bv    = (const float*)d_in[9];
    const float* w0    = (const float*)d_in[10];
    const float* b0    = (const float*)d_in[11];
    const float* ln1_g = (const float*)d_in[12];
    const float* ln1_b = (const float*)d_in[13];
    const float* ff1_w = (const float*)d_in[14];
    const float* ff1_b = (const float*)d_in[15];
    const float* ff2_w = (const float*)d_in[16];
    const float* ff2_b = (const float*)d_in[17];
    const float* ln2_g = (const float*)d_in[18];
    const float* ln2_b = (const float*)d_in[19];

    float* out = (float*)d_out;
    float* out_attn = out + (long long)BB * SS * DD;

    const int SM_NN = 2 * (128 * 36 + 32 * 136) * 4;   // 71680
    const int SM_FL = (128 * 68 + 2 * 64 * 68 + 2 * 64 * 72 + 128 * 68
                       + 1024 + 512 + 512) * 4;        // 149504

    if (!g_attr_set) {
        cudaFuncSetAttribute(gemm_tc2<128, 128, 0, 0>,
                             cudaFuncAttributeMaxDynamicSharedMemorySize, SM_NN);
        cudaFuncSetAttribute(gemm_tc2<128, 128, 0, 1>,
                             cudaFuncAttributeMaxDynamicSharedMemorySize, SM_NN);
        cudaFuncSetAttribute(gemm_tc2<128, 128, 1, 1>,
                             cudaFuncAttributeMaxDynamicSharedMemorySize, SM_NN);
        cudaFuncSetAttribute(flash_attn,
                             cudaFuncAttributeMaxDynamicSharedMemorySize, SM_FL);
        g_attr_set = 1;
    }

    float *pxq, *pxk, *pxv, *pw0r, *pff1r, *pff2r;
    float *pwq, *pwk, *pwv, *pq, *pk, *pv, *praw, *pconcat, *pffn1;
    cudaGetSymbolAddress((void**)&pxq, g_xq);
    cudaGetSymbolAddress((void**)&pxk, g_xk);
    cudaGetSymbolAddress((void**)&pxv, g_xv);
    cudaGetSymbolAddress((void**)&pw0r, g_w0r);
    cudaGetSymbolAddress((void**)&pff1r, g_ff1r);
    cudaGetSymbolAddress((void**)&pff2r, g_ff2r);
    cudaGetSymbolAddress((void**)&pwq, g_wq);
    cudaGetSymbolAddress((void**)&pwk, g_wk);
    cudaGetSymbolAddress((void**)&pwv, g_wv);
    cudaGetSymbolAddress((void**)&pq, g_q);
    cudaGetSymbolAddress((void**)&pk, g_k);
    cudaGetSymbolAddress((void**)&pv, g_v);
    cudaGetSymbolAddress((void**)&praw, g_att_raw);
    cudaGetSymbolAddress((void**)&pconcat, g_concat);
    cudaGetSymbolAddress((void**)&pffn1, g_ffn1);

    dim3 blk(256);
    const int MT = BB * SS;                          // 4096 token rows

    // prep: tf32-round inputs + weights
    round_copy<<<(BB * SS * DD) / 1024, blk>>>(x_q, pxq);
    round_copy<<<(BB * SS * DD) / 1024, blk>>>(x_k, pxk);
    round_copy<<<(BB * SS * DD) / 1024, blk>>>(x_v, pxv);
    round_copy<<<(DD * DD) / 1024, blk>>>(w0, pw0r);
    round_copy<<<(DD * DFF) / 1024, blk>>>(ff1_w, pff1r);
    round_copy<<<(DFF * DD) / 1024, blk>>>(ff2_w, pff2r);
    repack_kernel<<<(DD * DD) / 256, blk>>>(wq, wk, wv);

    // q/k/v projections (rounded outputs feed attention MMAs)
    gemm_tc2<128, 128, 0, 1><<<dim3(8, 32), blk, SM_NN>>>(pxq, pwq, bq, pq, DD, DD, DD, DD);
    gemm_tc2<128, 128, 0, 1><<<dim3(8, 32), blk, SM_NN>>>(pxk, pwk, bk, pk, DD, DD, DD, DD);
    gemm_tc2<128, 128, 0, 1><<<dim3(8, 32), blk, SM_NN>>>(pxv, pwv, bv, pv, DD, DD, DD, DD);

    // fused attention: scores + softmax + P@V; dumps last-head raw scores
    flash_attn<<<dim3(SS / 128, BB * HH), blk, SM_FL>>>(pq, pk, pv, mask, pconcat, praw);

    // last-head attention weights -> d_out second half
    softmax_out<<<BB * SS, blk>>>(praw, out_attn);

    // mha_out = concat @ w0 + b0  (reuse g_xq)
    gemm_tc2<128, 128, 0, 0><<<dim3(8, 32), blk, SM_NN>>>(pconcat, pw0r, b0, pxq, DD, DD, DD, DD);

    // sub1 = LN1(x_q + mha_out): exact -> g_k, rounded -> g_xk
    add_ln_kernel<<<MT, blk>>>(x_q, pxq, ln1_g, ln1_b, pk, pxk);

    // ffn1 = relu(sub1 @ ff1_w + ff1_b), rounded
    gemm_tc2<128, 128, 1, 1><<<dim3(32, 32), blk, SM_NN>>>(pxk, pff1r, ff1_b, pffn1, DD, DD, DFF, DFF);

    // ffn2 = ffn1 @ ff2_w + ff2_b  (reuse g_xv)
    gemm_tc2<128, 128, 0, 0><<<dim3(8, 32), blk, SM_NN>>>(pffn1, pff2r, ff2_b, pxv, DFF, DFF, DD, DD);

    // out = LN2(sub1 + ffn2) -> d_out first half
    add_ln_kernel<<<MT, blk>>>(pk, pxv, ln2_g, ln2_b, out, nullptr);
}